// round 16
// baseline (speedup 1.0000x reference)
#include <cuda_runtime.h>
#include <math.h>

#define NPIX 65536
#define NB   8

typedef unsigned long long ull;

__device__ __forceinline__ void ffma2(ull &d, ull a, ull b) {
    asm("fma.rn.f32x2 %0, %1, %2, %0;" : "+l"(d) : "l"(a), "l"(b));
}
__device__ __forceinline__ ull dup2(float x) {
    ull r; unsigned xi = __float_as_uint(x);
    asm("mov.b64 %0, {%1, %1};" : "=l"(r) : "r"(xi));
    return r;
}
__device__ __forceinline__ float2 unpk(ull d) {
    unsigned lo, hi;
    asm("mov.b64 {%0, %1}, %2;" : "=r"(lo), "=r"(hi) : "l"(d));
    return make_float2(__uint_as_float(lo), __uint_as_float(hi));
}
__device__ __forceinline__ unsigned smem_u32(const void* p) {
    unsigned a;
    asm("{ .reg .u64 t; cvta.to.shared.u64 t, %1; cvt.u32.u64 %0, t; }" : "=r"(a) : "l"(p));
    return a;
}
__device__ __forceinline__ void cp16(unsigned dst, const void* src) {
    asm volatile("cp.async.cg.shared.global [%0], [%1], 16;" :: "r"(dst), "l"(src));
}

// ---------------- scratch ----------------
__device__ float g_q [(size_t)NB * 64 * NPIX];   // (b, 64ch, n)  channel-major
__device__ float g_vc[(size_t)NB * 32 * NPIX];   // (b, 32ch, n)  channel-major
__device__ float g_sumexp[NB * 16];
__device__ float g_cross [NB * 16 * 32];

// ---------------- q projection (round-11 proven: 128px, 8og x 8outs) --------
__global__ void __launch_bounds__(256) qproj_kernel(const float* __restrict__ x,
                             const float* __restrict__ Wq,
                             const float* __restrict__ gq,
                             const float* __restrict__ bq) {
    __shared__ float w_sh[64 * 68];      // [c][o], pad 68 (16B-aligned rows)
    __shared__ float x_sh[16 * 128];
    const int t = threadIdx.x;
    const int b = blockIdx.y;
    const int pbase = blockIdx.x * 128;

    // fold: zero cross/sumexp accumulators (stream order protects atomics)
    if (blockIdx.x == 0 && blockIdx.y == 0) {
        for (int i = t; i < NB * 16 * 32; i += 256) g_cross[i] = 0.f;
        if (t < NB * 16) g_sumexp[t] = 0.f;
    }

    const float inv = rsqrtf(1.0f + 1e-5f);
    for (int i = t; i < 4096; i += 256) {
        int o = i >> 6, c = i & 63;
        w_sh[c * 68 + o] = Wq[i] * gq[o] * inv;
    }

    const int og = t >> 5;       // 0..7  (8 outputs each)
    const int pg = t & 31;       // 4 pixels

    ull acc2[16];
#pragma unroll
    for (int i = 0; i < 16; i++) acc2[i] = 0ull;

    const float* xb = x + ((size_t)b * 64) * NPIX + pbase;

#pragma unroll 1
    for (int c0 = 0; c0 < 64; c0 += 16) {
        __syncthreads();
        for (int i = t; i < 512; i += 256) {
            int cc = i >> 5, p4 = i & 31;
            ((float4*)x_sh)[i] = *(const float4*)(xb + (size_t)(c0 + cc) * NPIX + p4 * 4);
        }
        __syncthreads();
#pragma unroll
        for (int cc = 0; cc < 16; cc++) {
            float4 xv = ((float4*)x_sh)[cc * 32 + pg];
            ull bx = dup2(xv.x), by = dup2(xv.y), bz = dup2(xv.z), bw = dup2(xv.w);
            const ulonglong2* wr2 = (const ulonglong2*)(w_sh + (c0 + cc) * 68 + og * 8);
            ulonglong2 wa = wr2[0], wb = wr2[1];   // 2x LDS.128 (uniform)
            ffma2(acc2[0],  wa.x, bx); ffma2(acc2[1],  wa.x, by);
            ffma2(acc2[2],  wa.x, bz); ffma2(acc2[3],  wa.x, bw);
            ffma2(acc2[4],  wa.y, bx); ffma2(acc2[5],  wa.y, by);
            ffma2(acc2[6],  wa.y, bz); ffma2(acc2[7],  wa.y, bw);
            ffma2(acc2[8],  wb.x, bx); ffma2(acc2[9],  wb.x, by);
            ffma2(acc2[10], wb.x, bz); ffma2(acc2[11], wb.x, bw);
            ffma2(acc2[12], wb.y, bx); ffma2(acc2[13], wb.y, by);
            ffma2(acc2[14], wb.y, bz); ffma2(acc2[15], wb.y, bw);
        }
    }
    float* qb = g_q + ((size_t)b * 64 + og * 8) * NPIX + pbase + pg * 4;
#pragma unroll
    for (int p = 0; p < 4; p++) {
        float2 j0 = unpk(acc2[p*4+0]), j1 = unpk(acc2[p*4+1]);
        float2 j2 = unpk(acc2[p*4+2]), j3 = unpk(acc2[p*4+3]);
        float blo = bq[og * 8 + 2*p], bhi = bq[og * 8 + 2*p + 1];
        *(float4*)(qb + (size_t)(2*p)   * NPIX) = make_float4(j0.x+blo, j1.x+blo, j2.x+blo, j3.x+blo);
        *(float4*)(qb + (size_t)(2*p+1) * NPIX) = make_float4(j0.y+bhi, j1.y+bhi, j2.y+bhi, j3.y+bhi);
    }
}

// ---------------- k/v projection + fused cross (round-11 proven) ------------
__global__ void __launch_bounds__(192) kvproj_kernel(const float* __restrict__ x,
                              const float* __restrict__ Wk,
                              const float* __restrict__ Wv,
                              const float* __restrict__ gv,
                              const float* __restrict__ bv) {
    __shared__ float smem[6336];
    float* w_sh = smem;                  // [c][o], 48 outs pad 52 (16B rows)
    float* x_sh = smem + 3328;
    float* ek_sh = smem;                 // overlay after GEMM: [16][132]
    float* v_sh  = smem + 2112;          //                    [32][132]
    const int t = threadIdx.x;
    const int b = blockIdx.y;
    const int pbase = blockIdx.x * 128;

    const float inv = rsqrtf(1.0f + 1e-5f);
    for (int i = t; i < 3072; i += 192) {
        int o = i >> 6, c = i & 63;
        float val;
        if (o < 16) val = Wk[o * 64 + c];
        else { int vo = o - 16; val = Wv[vo * 64 + c] * gv[vo] * inv; }
        w_sh[c * 52 + o] = val;
    }

    const int og = t >> 5;       // 0..5 (8 outs each; 0-1 = k, 2-5 = v)
    const int pg = t & 31;

    ull acc2[16];
#pragma unroll
    for (int i = 0; i < 16; i++) acc2[i] = 0ull;

    const float* xb = x + ((size_t)b * 64) * NPIX + pbase;

#pragma unroll 1
    for (int c0 = 0; c0 < 64; c0 += 16) {
        __syncthreads();
        for (int i = t; i < 512; i += 192) {
            int cc = i >> 5, p4 = i & 31;
            ((float4*)x_sh)[i] = *(const float4*)(xb + (size_t)(c0 + cc) * NPIX + p4 * 4);
        }
        __syncthreads();
#pragma unroll
        for (int cc = 0; cc < 16; cc++) {
            float4 xv = ((float4*)x_sh)[cc * 32 + pg];
            ull bx = dup2(xv.x), by = dup2(xv.y), bz = dup2(xv.z), bw = dup2(xv.w);
            const ulonglong2* wr2 = (const ulonglong2*)(w_sh + (c0 + cc) * 52 + og * 8);
            ulonglong2 wa = wr2[0], wb = wr2[1];
            ffma2(acc2[0],  wa.x, bx); ffma2(acc2[1],  wa.x, by);
            ffma2(acc2[2],  wa.x, bz); ffma2(acc2[3],  wa.x, bw);
            ffma2(acc2[4],  wa.y, bx); ffma2(acc2[5],  wa.y, by);
            ffma2(acc2[6],  wa.y, bz); ffma2(acc2[7],  wa.y, bw);
            ffma2(acc2[8],  wb.x, bx); ffma2(acc2[9],  wb.x, by);
            ffma2(acc2[10], wb.x, bz); ffma2(acc2[11], wb.x, bw);
            ffma2(acc2[12], wb.y, bx); ffma2(acc2[13], wb.y, by);
            ffma2(acc2[14], wb.y, bz); ffma2(acc2[15], wb.y, bw);
        }
    }

    __syncthreads();

    if (og < 2) {
        float ps[8];
#pragma unroll
        for (int p = 0; p < 4; p++) {
            float2 j0 = unpk(acc2[p*4+0]), j1 = unpk(acc2[p*4+1]);
            float2 j2 = unpk(acc2[p*4+2]), j3 = unpk(acc2[p*4+3]);
            float e0 = __expf(j0.x), e1 = __expf(j1.x), e2 = __expf(j2.x), e3 = __expf(j3.x);
            ps[2*p] = e0 + e1 + e2 + e3;
            *(float4*)(ek_sh + (og * 8 + 2*p) * 132 + pg * 4) = make_float4(e0, e1, e2, e3);
            float f0 = __expf(j0.y), f1 = __expf(j1.y), f2 = __expf(j2.y), f3 = __expf(j3.y);
            ps[2*p+1] = f0 + f1 + f2 + f3;
            *(float4*)(ek_sh + (og * 8 + 2*p+1) * 132 + pg * 4) = make_float4(f0, f1, f2, f3);
        }
#pragma unroll
        for (int off = 16; off > 0; off >>= 1)
#pragma unroll
            for (int o = 0; o < 8; o++)
                ps[o] += __shfl_xor_sync(0xffffffffu, ps[o], off);
        if (pg == 0) {
#pragma unroll
            for (int o = 0; o < 8; o++)
                atomicAdd(&g_sumexp[b * 16 + og * 8 + o], ps[o]);
        }
    } else {
        const int vb = (og - 2) * 8;
#pragma unroll
        for (int p = 0; p < 4; p++) {
            float2 j0 = unpk(acc2[p*4+0]), j1 = unpk(acc2[p*4+1]);
            float2 j2 = unpk(acc2[p*4+2]), j3 = unpk(acc2[p*4+3]);
            float blo = bv[vb + 2*p], bhi = bv[vb + 2*p + 1];
            float4 slo = make_float4(j0.x+blo, j1.x+blo, j2.x+blo, j3.x+blo);
            float4 shi = make_float4(j0.y+bhi, j1.y+bhi, j2.y+bhi, j3.y+bhi);
            *(float4*)(g_vc + ((size_t)b * 32 + vb + 2*p)   * NPIX + pbase + pg * 4) = slo;
            *(float4*)(g_vc + ((size_t)b * 32 + vb + 2*p+1) * NPIX + pbase + pg * 4) = shi;
            *(float4*)(v_sh + (vb + 2*p)   * 132 + pg * 4) = slo;
            *(float4*)(v_sh + (vb + 2*p+1) * 132 + pg * 4) = shi;
        }
    }
    __syncthreads();

    for (int idx = t; idx < 512; idx += 192) {
        const int k = idx >> 5, v = idx & 31;
        const float* ekr = ek_sh + k * 132;
        const float* vr  = v_sh + v * 132;
        ull sa = 0ull, sb = 0ull;
#pragma unroll
        for (int p = 0; p < 128; p += 4) {
            ulonglong2 e  = *(const ulonglong2*)(ekr + p);
            ulonglong2 vv = *(const ulonglong2*)(vr + p);
            ffma2(sa, e.x, vv.x);
            ffma2(sb, e.y, vv.y);
        }
        float2 ua = unpk(sa), ub = unpk(sb);
        atomicAdd(&g_cross[b * 512 + idx], (ua.x + ua.y) + (ub.x + ub.y));
    }
}

// ---------------- output: 2-heads-per-thread + cp.async q double-buffer -----
// grid (4, 64, 8); block 256 = hdp(2) x vh(2) x px(64); tile 64x4 px
// q buffer rows padded to 68 floats (272 B, 16B-aligned) for cp.async.
__global__ void __launch_bounds__(256, 2) out_kernel(const float* __restrict__ bp,
                                                     const float* __restrict__ Wp,
                                                     float* __restrict__ out) {
    extern __shared__ float sh[];
    float* vt   = sh;             // [6 rows][66 x][36 ch-pad]  = 14256 floats
    float* lam  = sh + 14256;     // [16][44]                   = 704 floats
    float* qbuf = sh + 14960;     // 2 x [64 ch][68 px-pad]     = 8704 floats
    const int t = threadIdx.x;
    const int b = blockIdx.z;
    const int gx = blockIdx.x * 64;
    const int gy = blockIdx.y * 4;

    const unsigned qbuf_addr = smem_u32(qbuf);
    const float* qsrc_base = g_q + ((size_t)b * 64) * NPIX + gx;

    // issue cp.async q prefetch for ty=0 FIRST (overlaps lam + halo fill)
    {
        const float* qs = qsrc_base + (size_t)gy * 256;
        const unsigned qd = qbuf_addr;
        for (int i = t; i < 1024; i += 256) {
            int ch = i >> 4, p4 = i & 15;
            cp16(qd + (unsigned)(ch * 68 + p4 * 4) * 4, qs + (size_t)ch * NPIX + p4 * 4);
        }
        asm volatile("cp.async.commit_group;" ::: "memory");
    }

    // lamE built in-block: [cross/sumexp + bp | Wp | 0]
    for (int i = t; i < 704; i += 256) {
        int k = i / 44, col = i - k * 44;
        float val;
        if (col < 32)      val = g_cross[b * 512 + k * 32 + col] / g_sumexp[b * 16 + k] + bp[k];
        else if (col < 41) val = Wp[k * 9 + col - 32];
        else               val = 0.f;
        lam[i] = val;
    }

    // halo: lanes sweep pixels, 4-ch gathered per thread, STS.128 conflict-free
    for (int i = t; i < 3168; i += 256) {
        int c4 = i / 396;
        int pxi = i - c4 * 396;
        int row = pxi / 66, x = pxi - row * 66;
        int y = gy - 1 + row, xx = gx - 1 + x;
        float4 val = make_float4(0.f, 0.f, 0.f, 0.f);
        if ((unsigned)y < 256u && (unsigned)xx < 256u) {
            const float* src = g_vc + ((size_t)b * 32 + c4 * 4) * NPIX + y * 256 + xx;
            val.x = src[0];
            val.y = src[NPIX];
            val.z = src[2 * (size_t)NPIX];
            val.w = src[3 * (size_t)NPIX];
        }
        *(float4*)(vt + (row * 66 + x) * 36 + c4 * 4) = val;
    }
    asm volatile("cp.async.wait_group 0;" ::: "memory");
    __syncthreads();

    const int hdp = t >> 7, vh = (t >> 6) & 1, px = t & 63;
    const int h0 = hdp * 2, h1 = hdp * 2 + 1;

    float* o0base = out + ((size_t)b * 128 + h0 * 32 + vh * 16) * NPIX + gx + px;
    float* o1base = out + ((size_t)b * 128 + h1 * 32 + vh * 16) * NPIX + gx + px;

#pragma unroll 1
    for (int ty = 0; ty < 4; ty++) {
        // prefetch next row's q while computing this one
        if (ty < 3) {
            const float* qs = qsrc_base + (size_t)(gy + ty + 1) * 256;
            const unsigned qd = qbuf_addr + (unsigned)(((ty + 1) & 1) * 4352) * 4;
            for (int i = t; i < 1024; i += 256) {
                int ch = i >> 4, p4 = i & 15;
                cp16(qd + (unsigned)(ch * 68 + p4 * 4) * 4, qs + (size_t)ch * NPIX + p4 * 4);
            }
            asm volatile("cp.async.commit_group;" ::: "memory");
        }

        const float* qcur = qbuf + (ty & 1) * 4352;
        const float* q0 = qcur + (hdp * 32) * 68 + px;        // head h0 rows
        const float* q1 = qcur + (hdp * 32 + 16) * 68 + px;   // head h1 rows

        ull acc[2][8];
        ull racc[2][5];
#pragma unroll
        for (int h = 0; h < 2; h++) {
#pragma unroll
            for (int p = 0; p < 8; p++) acc[h][p] = 0ull;
#pragma unroll
            for (int p = 0; p < 5; p++) racc[h][p] = 0ull;
        }

        // fused content + r over k; q via LDS (lat 29), lam broadcast
#pragma unroll
        for (int kk = 0; kk < 16; kk++) {
            ull qa = dup2(q0[kk * 68]);
            ull qb = dup2(q1[kk * 68]);
            const float* le = lam + kk * 44;
            ulonglong2 l0 = *(const ulonglong2*)(le + vh * 16);
            ulonglong2 l1 = *(const ulonglong2*)(le + vh * 16 + 4);
            ulonglong2 l2 = *(const ulonglong2*)(le + vh * 16 + 8);
            ulonglong2 l3 = *(const ulonglong2*)(le + vh * 16 + 12);
            ulonglong2 r0 = *(const ulonglong2*)(le + 32);
            ulonglong2 r1 = *(const ulonglong2*)(le + 36);
            ull r2v = *(const ull*)(le + 40);

            ffma2(acc[0][0], l0.x, qa); ffma2(acc[0][1], l0.y, qa);
            ffma2(acc[0][2], l1.x, qa); ffma2(acc[0][3], l1.y, qa);
            ffma2(acc[0][4], l2.x, qa); ffma2(acc[0][5], l2.y, qa);
            ffma2(acc[0][6], l3.x, qa); ffma2(acc[0][7], l3.y, qa);
            ffma2(racc[0][0], r0.x, qa); ffma2(racc[0][1], r0.y, qa);
            ffma2(racc[0][2], r1.x, qa); ffma2(racc[0][3], r1.y, qa);
            ffma2(racc[0][4], r2v, qa);

            ffma2(acc[1][0], l0.x, qb); ffma2(acc[1][1], l0.y, qb);
            ffma2(acc[1][2], l1.x, qb); ffma2(acc[1][3], l1.y, qb);
            ffma2(acc[1][4], l2.x, qb); ffma2(acc[1][5], l2.y, qb);
            ffma2(acc[1][6], l3.x, qb); ffma2(acc[1][7], l3.y, qb);
            ffma2(racc[1][0], r0.x, qb); ffma2(racc[1][1], r0.y, qb);
            ffma2(racc[1][2], r1.x, qb); ffma2(racc[1][3], r1.y, qb);
            ffma2(racc[1][4], r2v, qb);
        }

        float rr[2][10];
#pragma unroll
        for (int h = 0; h < 2; h++)
#pragma unroll
            for (int j2 = 0; j2 < 5; j2++) {
                float2 u = unpk(racc[h][j2]);
                rr[h][2*j2] = u.x; rr[h][2*j2+1] = u.y;
            }

        // position term: one v-neighborhood load feeds both heads
#pragma unroll
        for (int dy = 0; dy < 3; dy++) {
            const float* vrow = vt + ((ty + dy) * 66 + px) * 36 + vh * 16;
#pragma unroll
            for (int dx = 0; dx < 3; dx++) {
                const float* vp = vrow + dx * 36;
                ulonglong2 va = *(const ulonglong2*)(vp);
                ulonglong2 vb2 = *(const ulonglong2*)(vp + 4);
                ulonglong2 vc2 = *(const ulonglong2*)(vp + 8);
                ulonglong2 vd2 = *(const ulonglong2*)(vp + 12);
                ull w0 = dup2(rr[0][dy * 3 + dx]);
                ffma2(acc[0][0], va.x, w0);  ffma2(acc[0][1], va.y, w0);
                ffma2(acc[0][2], vb2.x, w0); ffma2(acc[0][3], vb2.y, w0);
                ffma2(acc[0][4], vc2.x, w0); ffma2(acc[0][5], vc2.y, w0);
                ffma2(acc[0][6], vd2.x, w0); ffma2(acc[0][7], vd2.y, w0);
                ull w1 = dup2(rr[1][dy * 3 + dx]);
                ffma2(acc[1][0], va.x, w1);  ffma2(acc[1][1], va.y, w1);
                ffma2(acc[1][2], vb2.x, w1); ffma2(acc[1][3], vb2.y, w1);
                ffma2(acc[1][4], vc2.x, w1); ffma2(acc[1][5], vc2.y, w1);
                ffma2(acc[1][6], vd2.x, w1); ffma2(acc[1][7], vd2.y, w1);
            }
        }

        const size_t rowoff = (size_t)(gy + ty) * 256;
        float* o0 = o0base + rowoff;
        float* o1 = o1base + rowoff;
#pragma unroll
        for (int p = 0; p < 8; p++) {
            float2 u0 = unpk(acc[0][p]);
            o0[(size_t)(2*p)   * NPIX] = u0.x;
            o0[(size_t)(2*p+1) * NPIX] = u0.y;
            float2 u1 = unpk(acc[1][p]);
            o1[(size_t)(2*p)   * NPIX] = u1.x;
            o1[(size_t)(2*p+1) * NPIX] = u1.y;
        }

        if (ty < 3) {
            asm volatile("cp.async.wait_group 0;" ::: "memory");
            __syncthreads();
        }
    }
}

// ---------------- launch (3 kernels) ----------------
extern "C" void kernel_launch(void* const* d_in, const int* in_sizes, int n_in,
                              void* d_out, int out_size) {
    const float* x  = (const float*)d_in[0];
    const float* Wq = (const float*)d_in[1];
    const float* gq = (const float*)d_in[2];
    const float* bq = (const float*)d_in[3];
    const float* Wk = (const float*)d_in[4];
    const float* Wv = (const float*)d_in[5];
    const float* gv = (const float*)d_in[6];
    const float* bv = (const float*)d_in[7];
    const float* Wp = (const float*)d_in[8];
    const float* bp = (const float*)d_in[9];
    float* out = (float*)d_out;

    const int out_smem = (14256 + 704 + 8704) * 4;   // 94656 B
    cudaFuncSetAttribute(out_kernel, cudaFuncAttributeMaxDynamicSharedMemorySize, out_smem);

    qproj_kernel<<<dim3(NPIX / 128, NB), 256>>>(x, Wq, gq, bq);   // also zeros accum
    kvproj_kernel<<<dim3(NPIX / 128, NB), 192>>>(x, Wk, Wv, gv, bv);  // + fused cross
    out_kernel<<<dim3(4, 64, NB), 256, out_smem>>>(bp, Wp, out);
}

// round 17
// speedup vs baseline: 1.5138x; 1.5138x over previous
#include <cuda_runtime.h>
#include <math.h>

#define NPIX 65536
#define NB   8

typedef unsigned long long ull;

__device__ __forceinline__ void ffma2(ull &d, ull a, ull b) {
    asm("fma.rn.f32x2 %0, %1, %2, %0;" : "+l"(d) : "l"(a), "l"(b));
}
__device__ __forceinline__ ull dup2(float x) {
    ull r; unsigned xi = __float_as_uint(x);
    asm("mov.b64 %0, {%1, %1};" : "=l"(r) : "r"(xi));
    return r;
}
__device__ __forceinline__ float2 unpk(ull d) {
    unsigned lo, hi;
    asm("mov.b64 {%0, %1}, %2;" : "=r"(lo), "=r"(hi) : "l"(d));
    return make_float2(__uint_as_float(lo), __uint_as_float(hi));
}

// ---------------- scratch ----------------
__device__ float g_q [(size_t)NB * 64 * NPIX];   // (b, 64ch, n)  channel-major
__device__ float g_vc[(size_t)NB * 32 * NPIX];   // (b, 32ch, n)  channel-major
__device__ float g_sumexp[NB * 16];
__device__ float g_cross [NB * 16 * 32];

// ---------------- q projection: 128px tile, 8og x 8outs; 16B weight loads ---
__global__ void __launch_bounds__(256) qproj_kernel(const float* __restrict__ x,
                             const float* __restrict__ Wq,
                             const float* __restrict__ gq,
                             const float* __restrict__ bq) {
    __shared__ float w_sh[64 * 68];      // [c][o], pad 68 (16B-aligned rows)
    __shared__ float x_sh[16 * 128];
    const int t = threadIdx.x;
    const int b = blockIdx.y;
    const int pbase = blockIdx.x * 128;

    // fold: zero cross/sumexp accumulators (stream order protects atomics)
    if (blockIdx.x == 0 && blockIdx.y == 0) {
        for (int i = t; i < NB * 16 * 32; i += 256) g_cross[i] = 0.f;
        if (t < NB * 16) g_sumexp[t] = 0.f;
    }

    const float inv = rsqrtf(1.0f + 1e-5f);
    for (int i = t; i < 4096; i += 256) {
        int o = i >> 6, c = i & 63;
        w_sh[c * 68 + o] = Wq[i] * gq[o] * inv;
    }

    const int og = t >> 5;       // 0..7  (8 outputs each)
    const int pg = t & 31;       // 4 pixels

    ull acc2[16];
#pragma unroll
    for (int i = 0; i < 16; i++) acc2[i] = 0ull;

    const float* xb = x + ((size_t)b * 64) * NPIX + pbase;

#pragma unroll 1
    for (int c0 = 0; c0 < 64; c0 += 16) {
        __syncthreads();
        for (int i = t; i < 512; i += 256) {
            int cc = i >> 5, p4 = i & 31;
            ((float4*)x_sh)[i] = *(const float4*)(xb + (size_t)(c0 + cc) * NPIX + p4 * 4);
        }
        __syncthreads();
#pragma unroll
        for (int cc = 0; cc < 16; cc++) {
            float4 xv = ((float4*)x_sh)[cc * 32 + pg];
            ull bx = dup2(xv.x), by = dup2(xv.y), bz = dup2(xv.z), bw = dup2(xv.w);
            const ulonglong2* wr2 = (const ulonglong2*)(w_sh + (c0 + cc) * 68 + og * 8);
            ulonglong2 wa = wr2[0], wb = wr2[1];   // 2x LDS.128 (uniform)
            ffma2(acc2[0],  wa.x, bx); ffma2(acc2[1],  wa.x, by);
            ffma2(acc2[2],  wa.x, bz); ffma2(acc2[3],  wa.x, bw);
            ffma2(acc2[4],  wa.y, bx); ffma2(acc2[5],  wa.y, by);
            ffma2(acc2[6],  wa.y, bz); ffma2(acc2[7],  wa.y, bw);
            ffma2(acc2[8],  wb.x, bx); ffma2(acc2[9],  wb.x, by);
            ffma2(acc2[10], wb.x, bz); ffma2(acc2[11], wb.x, bw);
            ffma2(acc2[12], wb.y, bx); ffma2(acc2[13], wb.y, by);
            ffma2(acc2[14], wb.y, bz); ffma2(acc2[15], wb.y, bw);
        }
    }
    float* qb = g_q + ((size_t)b * 64 + og * 8) * NPIX + pbase + pg * 4;
#pragma unroll
    for (int p = 0; p < 4; p++) {
        float2 j0 = unpk(acc2[p*4+0]), j1 = unpk(acc2[p*4+1]);
        float2 j2 = unpk(acc2[p*4+2]), j3 = unpk(acc2[p*4+3]);
        float blo = bq[og * 8 + 2*p], bhi = bq[og * 8 + 2*p + 1];
        *(float4*)(qb + (size_t)(2*p)   * NPIX) = make_float4(j0.x+blo, j1.x+blo, j2.x+blo, j3.x+blo);
        *(float4*)(qb + (size_t)(2*p+1) * NPIX) = make_float4(j0.y+bhi, j1.y+bhi, j2.y+bhi, j3.y+bhi);
    }
}

// ---------------- k/v projection + FUSED cross reduction --------------------
__global__ void __launch_bounds__(192) kvproj_kernel(const float* __restrict__ x,
                              const float* __restrict__ Wk,
                              const float* __restrict__ Wv,
                              const float* __restrict__ gv,
                              const float* __restrict__ bv) {
    __shared__ float smem[6336];
    float* w_sh = smem;                  // [c][o], 48 outs pad 52 (16B rows)
    float* x_sh = smem + 3328;
    float* ek_sh = smem;                 // overlay after GEMM: [16][132]
    float* v_sh  = smem + 2112;          //                    [32][132]
    const int t = threadIdx.x;
    const int b = blockIdx.y;
    const int pbase = blockIdx.x * 128;

    const float inv = rsqrtf(1.0f + 1e-5f);
    for (int i = t; i < 3072; i += 192) {
        int o = i >> 6, c = i & 63;
        float val;
        if (o < 16) val = Wk[o * 64 + c];
        else { int vo = o - 16; val = Wv[vo * 64 + c] * gv[vo] * inv; }
        w_sh[c * 52 + o] = val;
    }

    const int og = t >> 5;       // 0..5 (8 outs each; 0-1 = k, 2-5 = v)
    const int pg = t & 31;

    ull acc2[16];
#pragma unroll
    for (int i = 0; i < 16; i++) acc2[i] = 0ull;

    const float* xb = x + ((size_t)b * 64) * NPIX + pbase;

#pragma unroll 1
    for (int c0 = 0; c0 < 64; c0 += 16) {
        __syncthreads();
        for (int i = t; i < 512; i += 192) {
            int cc = i >> 5, p4 = i & 31;
            ((float4*)x_sh)[i] = *(const float4*)(xb + (size_t)(c0 + cc) * NPIX + p4 * 4);
        }
        __syncthreads();
#pragma unroll
        for (int cc = 0; cc < 16; cc++) {
            float4 xv = ((float4*)x_sh)[cc * 32 + pg];
            ull bx = dup2(xv.x), by = dup2(xv.y), bz = dup2(xv.z), bw = dup2(xv.w);
            const ulonglong2* wr2 = (const ulonglong2*)(w_sh + (c0 + cc) * 52 + og * 8);
            ulonglong2 wa = wr2[0], wb = wr2[1];   // 2x LDS.128 (uniform)
            ffma2(acc2[0],  wa.x, bx); ffma2(acc2[1],  wa.x, by);
            ffma2(acc2[2],  wa.x, bz); ffma2(acc2[3],  wa.x, bw);
            ffma2(acc2[4],  wa.y, bx); ffma2(acc2[5],  wa.y, by);
            ffma2(acc2[6],  wa.y, bz); ffma2(acc2[7],  wa.y, bw);
            ffma2(acc2[8],  wb.x, bx); ffma2(acc2[9],  wb.x, by);
            ffma2(acc2[10], wb.x, bz); ffma2(acc2[11], wb.x, bw);
            ffma2(acc2[12], wb.y, bx); ffma2(acc2[13], wb.y, by);
            ffma2(acc2[14], wb.y, bz); ffma2(acc2[15], wb.y, bw);
        }
    }

    // all reads of w_sh/x_sh complete before the overlay is written
    __syncthreads();

    if (og < 2) {
        // k logits -> exp; store to smem (NOT gmem); sumexp reduce
        float ps[8];
#pragma unroll
        for (int p = 0; p < 4; p++) {
            float2 j0 = unpk(acc2[p*4+0]), j1 = unpk(acc2[p*4+1]);
            float2 j2 = unpk(acc2[p*4+2]), j3 = unpk(acc2[p*4+3]);
            float e0 = __expf(j0.x), e1 = __expf(j1.x), e2 = __expf(j2.x), e3 = __expf(j3.x);
            ps[2*p] = e0 + e1 + e2 + e3;
            *(float4*)(ek_sh + (og * 8 + 2*p) * 132 + pg * 4) = make_float4(e0, e1, e2, e3);
            float f0 = __expf(j0.y), f1 = __expf(j1.y), f2 = __expf(j2.y), f3 = __expf(j3.y);
            ps[2*p+1] = f0 + f1 + f2 + f3;
            *(float4*)(ek_sh + (og * 8 + 2*p+1) * 132 + pg * 4) = make_float4(f0, f1, f2, f3);
        }
#pragma unroll
        for (int off = 16; off > 0; off >>= 1)
#pragma unroll
            for (int o = 0; o < 8; o++)
                ps[o] += __shfl_xor_sync(0xffffffffu, ps[o], off);
        if (pg == 0) {
#pragma unroll
            for (int o = 0; o < 8; o++)
                atomicAdd(&g_sumexp[b * 16 + og * 8 + o], ps[o]);
        }
    } else {
        const int vb = (og - 2) * 8;
#pragma unroll
        for (int p = 0; p < 4; p++) {
            float2 j0 = unpk(acc2[p*4+0]), j1 = unpk(acc2[p*4+1]);
            float2 j2 = unpk(acc2[p*4+2]), j3 = unpk(acc2[p*4+3]);
            float blo = bv[vb + 2*p], bhi = bv[vb + 2*p + 1];
            float4 slo = make_float4(j0.x+blo, j1.x+blo, j2.x+blo, j3.x+blo);
            float4 shi = make_float4(j0.y+bhi, j1.y+bhi, j2.y+bhi, j3.y+bhi);
            *(float4*)(g_vc + ((size_t)b * 32 + vb + 2*p)   * NPIX + pbase + pg * 4) = slo;
            *(float4*)(g_vc + ((size_t)b * 32 + vb + 2*p+1) * NPIX + pbase + pg * 4) = shi;
            *(float4*)(v_sh + (vb + 2*p)   * 132 + pg * 4) = slo;
            *(float4*)(v_sh + (vb + 2*p+1) * 132 + pg * 4) = shi;
        }
    }
    __syncthreads();

    // fused cross: 512 (k,v) pairs over 192 threads; ek row uniform (bcast)
    for (int idx = t; idx < 512; idx += 192) {
        const int k = idx >> 5, v = idx & 31;
        const float* ekr = ek_sh + k * 132;
        const float* vr  = v_sh + v * 132;
        ull sa = 0ull, sb = 0ull;
#pragma unroll
        for (int p = 0; p < 128; p += 4) {
            ulonglong2 e  = *(const ulonglong2*)(ekr + p);
            ulonglong2 vv = *(const ulonglong2*)(vr + p);
            ffma2(sa, e.x, vv.x);
            ffma2(sb, e.y, vv.y);
        }
        float2 ua = unpk(sa), ub = unpk(sb);
        atomicAdd(&g_cross[b * 512 + idx], (ua.x + ua.y) + (ub.x + ub.y));
    }
}

// ---------------- output: 2-heads-per-thread, shared LDS amortized ----------
// grid (4, 64, 8); block 256 = hdp(2) x vh(2) x px(64); tile 64x4 px
__global__ void __launch_bounds__(256, 2) out_kernel(const float* __restrict__ bp,
                                                     const float* __restrict__ Wp,
                                                     float* __restrict__ out) {
    extern __shared__ float sh[];
    float* vt  = sh;            // [6 rows][66 x][36 ch-pad]  = 14256 floats
    float* lam = sh + 14256;    // [16][44]                   = 704 floats
    const int t = threadIdx.x;
    const int b = blockIdx.z;
    const int gx = blockIdx.x * 64;
    const int gy = blockIdx.y * 4;

    // lamE built in-block: [cross/sumexp + bp | Wp | 0]
    for (int i = t; i < 704; i += 256) {
        int k = i / 44, col = i - k * 44;
        float val;
        if (col < 32)      val = g_cross[b * 512 + k * 32 + col] / g_sumexp[b * 16 + k] + bp[k];
        else if (col < 41) val = Wp[k * 9 + col - 32];
        else               val = 0.f;
        lam[i] = val;
    }

    // halo: lanes sweep pixels, 4-ch gathered per thread, STS.128 conflict-free
    for (int i = t; i < 3168; i += 256) {
        int c4 = i / 396;                 // 0..7 (channel quad)
        int pxi = i - c4 * 396;           // 0..395
        int row = pxi / 66, x = pxi - row * 66;
        int y = gy - 1 + row, xx = gx - 1 + x;
        float4 val = make_float4(0.f, 0.f, 0.f, 0.f);
        if ((unsigned)y < 256u && (unsigned)xx < 256u) {
            const float* src = g_vc + ((size_t)b * 32 + c4 * 4) * NPIX + y * 256 + xx;
            val.x = src[0];
            val.y = src[NPIX];
            val.z = src[2 * (size_t)NPIX];
            val.w = src[3 * (size_t)NPIX];
        }
        *(float4*)(vt + (row * 66 + x) * 36 + c4 * 4) = val;
    }
    __syncthreads();

    const int hdp = t >> 7, vh = (t >> 6) & 1, px = t & 63;
    const int h0 = hdp * 2, h1 = hdp * 2 + 1;

    const float* q0base = g_q + ((size_t)b * 64 + h0 * 16) * NPIX + gx + px;
    const float* q1base = g_q + ((size_t)b * 64 + h1 * 16) * NPIX + gx + px;
    float* o0base = out + ((size_t)b * 128 + h0 * 32 + vh * 16) * NPIX + gx + px;
    float* o1base = out + ((size_t)b * 128 + h1 * 32 + vh * 16) * NPIX + gx + px;

#pragma unroll 1
    for (int ty = 0; ty < 4; ty++) {
        const size_t rowoff = (size_t)(gy + ty) * 256;
        const float* q0 = q0base + rowoff;
        const float* q1 = q1base + rowoff;

        ull acc[2][8];      // [head][v-pair]
        ull racc[2][5];     // [head][r-pair]
#pragma unroll
        for (int h = 0; h < 2; h++) {
#pragma unroll
            for (int p = 0; p < 8; p++) acc[h][p] = 0ull;
#pragma unroll
            for (int p = 0; p < 5; p++) racc[h][p] = 0ull;
        }

        // fused content + r over k; lam loads shared across both heads
#pragma unroll
        for (int kk = 0; kk < 16; kk++) {
            ull qa = dup2(__ldg(q0 + (size_t)kk * NPIX));
            ull qb = dup2(__ldg(q1 + (size_t)kk * NPIX));
            const float* le = lam + kk * 44;
            ulonglong2 l0 = *(const ulonglong2*)(le + vh * 16);
            ulonglong2 l1 = *(const ulonglong2*)(le + vh * 16 + 4);
            ulonglong2 l2 = *(const ulonglong2*)(le + vh * 16 + 8);
            ulonglong2 l3 = *(const ulonglong2*)(le + vh * 16 + 12);
            ulonglong2 r0 = *(const ulonglong2*)(le + 32);
            ulonglong2 r1 = *(const ulonglong2*)(le + 36);
            ull r2v = *(const ull*)(le + 40);

            ffma2(acc[0][0], l0.x, qa); ffma2(acc[0][1], l0.y, qa);
            ffma2(acc[0][2], l1.x, qa); ffma2(acc[0][3], l1.y, qa);
            ffma2(acc[0][4], l2.x, qa); ffma2(acc[0][5], l2.y, qa);
            ffma2(acc[0][6], l3.x, qa); ffma2(acc[0][7], l3.y, qa);
            ffma2(racc[0][0], r0.x, qa); ffma2(racc[0][1], r0.y, qa);
            ffma2(racc[0][2], r1.x, qa); ffma2(racc[0][3], r1.y, qa);
            ffma2(racc[0][4], r2v, qa);

            ffma2(acc[1][0], l0.x, qb); ffma2(acc[1][1], l0.y, qb);
            ffma2(acc[1][2], l1.x, qb); ffma2(acc[1][3], l1.y, qb);
            ffma2(acc[1][4], l2.x, qb); ffma2(acc[1][5], l2.y, qb);
            ffma2(acc[1][6], l3.x, qb); ffma2(acc[1][7], l3.y, qb);
            ffma2(racc[1][0], r0.x, qb); ffma2(racc[1][1], r0.y, qb);
            ffma2(racc[1][2], r1.x, qb); ffma2(racc[1][3], r1.y, qb);
            ffma2(racc[1][4], r2v, qb);
        }

        // unpack conv weights r for both heads
        float rr[2][10];
#pragma unroll
        for (int h = 0; h < 2; h++)
#pragma unroll
            for (int j2 = 0; j2 < 5; j2++) {
                float2 u = unpk(racc[h][j2]);
                rr[h][2*j2] = u.x; rr[h][2*j2+1] = u.y;
            }

        // position term: one v-neighborhood load feeds both heads
#pragma unroll
        for (int dy = 0; dy < 3; dy++) {
            const float* vrow = vt + ((ty + dy) * 66 + px) * 36 + vh * 16;
#pragma unroll
            for (int dx = 0; dx < 3; dx++) {
                const float* vp = vrow + dx * 36;
                ulonglong2 va = *(const ulonglong2*)(vp);
                ulonglong2 vb2 = *(const ulonglong2*)(vp + 4);
                ulonglong2 vc2 = *(const ulonglong2*)(vp + 8);
                ulonglong2 vd2 = *(const ulonglong2*)(vp + 12);
                ull w0 = dup2(rr[0][dy * 3 + dx]);
                ffma2(acc[0][0], va.x, w0);  ffma2(acc[0][1], va.y, w0);
                ffma2(acc[0][2], vb2.x, w0); ffma2(acc[0][3], vb2.y, w0);
                ffma2(acc[0][4], vc2.x, w0); ffma2(acc[0][5], vc2.y, w0);
                ffma2(acc[0][6], vd2.x, w0); ffma2(acc[0][7], vd2.y, w0);
                ull w1 = dup2(rr[1][dy * 3 + dx]);
                ffma2(acc[1][0], va.x, w1);  ffma2(acc[1][1], va.y, w1);
                ffma2(acc[1][2], vb2.x, w1); ffma2(acc[1][3], vb2.y, w1);
                ffma2(acc[1][4], vc2.x, w1); ffma2(acc[1][5], vc2.y, w1);
                ffma2(acc[1][6], vd2.x, w1); ffma2(acc[1][7], vd2.y, w1);
            }
        }

        float* o0 = o0base + rowoff;
        float* o1 = o1base + rowoff;
#pragma unroll
        for (int p = 0; p < 8; p++) {
            float2 u0 = unpk(acc[0][p]);
            o0[(size_t)(2*p)   * NPIX] = u0.x;
            o0[(size_t)(2*p+1) * NPIX] = u0.y;
            float2 u1 = unpk(acc[1][p]);
            o1[(size_t)(2*p)   * NPIX] = u1.x;
            o1[(size_t)(2*p+1) * NPIX] = u1.y;
        }
    }
}

// ---------------- launch (3 kernels) ----------------
extern "C" void kernel_launch(void* const* d_in, const int* in_sizes, int n_in,
                              void* d_out, int out_size) {
    const float* x  = (const float*)d_in[0];
    const float* Wq = (const float*)d_in[1];
    const float* gq = (const float*)d_in[2];
    const float* bq = (const float*)d_in[3];
    const float* Wk = (const float*)d_in[4];
    const float* Wv = (const float*)d_in[5];
    const float* gv = (const float*)d_in[6];
    const float* bv = (const float*)d_in[7];
    const float* Wp = (const float*)d_in[8];
    const float* bp = (const float*)d_in[9];
    float* out = (float*)d_out;

    const int out_smem = (14256 + 704) * 4;       // 59840 B
    cudaFuncSetAttribute(out_kernel, cudaFuncAttributeMaxDynamicSharedMemorySize, out_smem);

    qproj_kernel<<<dim3(NPIX / 128, NB), 256>>>(x, Wq, gq, bq);   // also zeros accum
    kvproj_kernel<<<dim3(NPIX / 128, NB), 192>>>(x, Wk, Wv, gv, bv);  // + fused cross
    out_kernel<<<dim3(4, 64, NB), 256, out_smem>>>(bp, Wp, out);
}